// round 16
// baseline (speedup 1.0000x reference)
#include <cuda_runtime.h>
#include <cuda_bf16.h>
#include <cuda_fp16.h>
#include <cstdint>
#include <math.h>

#define BB 8
#define LL 1024
#define DD 768
#define INV_SCALE 0.03608439182435161f  /* 1/sqrt(768) */

// ---------------------------------------------------------------------------
// scratch (device globals; no allocation)
// ---------------------------------------------------------------------------
__device__ __half s_lhs_h[BB * LL * DD], s_lhs_l[BB * LL * DD];   // proj A fp16 hi/lo
__device__ __half s_rhs_h[BB * LL * DD], s_rhs_l[BB * LL * DD];
__device__ __half s_lhsT_h[BB * DD * LL];   // apply B (fp16, single, transposed)
__device__ __half s_rhsT_h[BB * DD * LL];
__device__ __half s_Wl_h[DD * DD];          // W fp16 single
__device__ __half s_Wr_h[DD * DD];
__device__ __half g_L_h[BB * LL * DD];   // tanh(lhs@Wl) fp16 single
__device__ __half g_R_h[BB * LL * DD];   // tanh(rhs@Wr) fp16 single
__device__ __half g_P1[BB * LL * LL];    // row-softmax probs fp16 [l][r]
__device__ __half g_P2T[BB * LL * LL];   // col-softmax probs fp16, transposed [r][l]
__device__ float g_S[BB * LL * LL];
__device__ float2 g_prow[8][BB * LL];    // per-block row partials [col-block x][row]
__device__ float2 g_pcol[8][BB * LL];    // per-block col partials [row-block y][col]

// dependency counters
#define CI_PREP_L 0     /* 64 entries [by128], target 2 */
#define CI_PREP_R 64    /* 64 entries, target 2 */
#define CI_W 128        /* 1 entry, target 32 */
#define CI_PROJ 144     /* 128 entries [z*64+by], target 6 */
#define CI_SROW 272     /* 64 [bz*8+y], target 8 */
#define CI_SCOL 336     /* 64 [bz*8+x], target 8 */
#define CI_P1 400       /* 64 [bz*8+yb], target 8 */
#define CI_P2 464       /* 64 [bz*8+xb], target 8 */
#define CI_XT 528       /* 16 [side*8+b], target 16 */
#define NCTR 544
__device__ int c_all[NCTR];

__device__ __forceinline__ float fast_tanh(float x) {
    return 1.0f - __fdividef(2.0f, __expf(2.0f * x) + 1.0f);
}

__device__ __forceinline__ uint32_t smem_to_u32(const void* p) {
    uint32_t a;
    asm("{ .reg .u64 t; cvta.to.shared.u64 t, %1; cvt.u32.u64 %0, t; }"
        : "=r"(a) : "l"(p));
    return a;
}

__device__ __forceinline__ void merge_ms(float& m, float& s, float om, float os) {
    const float nm = fmaxf(m, om);
    s = s * __expf(m - nm) + os * __expf(om - nm);
    m = nm;
}

__device__ __forceinline__ void wait_ge(int* ctr, int target) {
    while (atomicAdd(ctr, 0) < target) __nanosleep(64);
}

// ---------------------------------------------------------------------------
// MMA helpers
// ---------------------------------------------------------------------------
__device__ __forceinline__ void ldsm4(uint32_t* r, uint32_t addr) {
    asm volatile("ldmatrix.sync.aligned.m8n8.x4.shared.b16 {%0,%1,%2,%3}, [%4];"
                 : "=r"(r[0]), "=r"(r[1]), "=r"(r[2]), "=r"(r[3]) : "r"(addr));
}

__device__ __forceinline__ void mma16816_f16(float* d, const uint32_t* a,
                                             uint32_t b0, uint32_t b1) {
    asm volatile(
        "mma.sync.aligned.m16n8k16.row.col.f32.f16.f16.f32 "
        "{%0,%1,%2,%3}, {%4,%5,%6,%7}, {%8,%9}, {%0,%1,%2,%3};"
        : "+f"(d[0]), "+f"(d[1]), "+f"(d[2]), "+f"(d[3])
        : "r"(a[0]), "r"(a[1]), "r"(a[2]), "r"(a[3]), "r"(b0), "r"(b1));
}

#define CP_ASYNC16(saddr, gptr) \
    asm volatile("cp.async.cg.shared.global [%0], [%1], 16;" \
        :: "r"(saddr), "l"(gptr) : "memory")
#define CP_COMMIT() asm volatile("cp.async.commit_group;" ::: "memory")
#define CP_WAIT(n) asm volatile("cp.async.wait_group %0;" :: "n"(n) : "memory")

// 64B-row tile (K-chunk 32 b16 elems)
__device__ __forceinline__ uint32_t tile_addr(uint32_t matbase, int row, int chunk) {
    int swz = chunk ^ (row & 3) ^ ((row >> 2) & 1);
    return matbase + row * 64 + swz * 16;
}
__device__ __forceinline__ uint32_t frag_addr(uint32_t matbase, int baserow,
                                              int kg, int lane) {
    int row = baserow + (lane & 7) + ((lane >> 3) & 1) * 8;
    int chunk = kg * 2 + ((lane >> 4) & 1);
    return tile_addr(matbase, row, chunk);
}
// 128B-row tile (fp16 K-chunk 64)
__device__ __forceinline__ uint32_t tile2_addr(uint32_t matbase, int row, int chunk) {
    int swz = chunk ^ (row & 7);
    return matbase + row * 128 + swz * 16;
}
__device__ __forceinline__ uint32_t frag2_addr(uint32_t matbase, int baserow,
                                               int kg, int lane) {
    int row = baserow + (lane & 7) + ((lane >> 3) & 1) * 8;
    int chunk = kg * 2 + ((lane >> 4) & 1);
    return tile2_addr(matbase, row, chunk);
}

#define MAT_BYTES 8192
#define STAGE_P 24576   /* proj: 3 matrices x 8 KB */
#define MAT2_BYTES 16384
#define STAGEA 32768    /* scores: 2 matrices x 16 KB */
#define STAGE_AP 24576  /* apply: A 16 KB + B 8 KB */
#define SMEM_DYN (3 * STAGEA)   /* 96 KB, shared by all phases */

// fp16 asym-2 proj mainloop: (Ah + Al) @ Wh^T, K-chunk 32
__device__ __forceinline__ void f16x2_mainloop(
    uint32_t sb, int tid, int lane, int warp_m, int warp_n,
    const __half* Ah, const __half* Al, const __half* Wh,
    int ldk, int nch, float acc[2][8][4])
{
    const __half* mats[3] = {Ah, Al, Wh};
    const int r0a = tid >> 2, c0a = tid & 3;
    const int r0b = (tid + 256) >> 2;

    auto load_chunk = [&](int slot, int k) {
        const uint32_t base = sb + slot * STAGE_P;
        const long koff = (long)k * 32;
#pragma unroll
        for (int mat = 0; mat < 3; ++mat) {
            const __half* g = mats[mat] + koff;
            const uint32_t mb = base + mat * MAT_BYTES;
            CP_ASYNC16(tile_addr(mb, r0a, c0a), g + (long)r0a * ldk + c0a * 8);
            CP_ASYNC16(tile_addr(mb, r0b, c0a), g + (long)r0b * ldk + c0a * 8);
        }
        CP_COMMIT();
    };

    load_chunk(0, 0);
    load_chunk(1, 1);

#pragma unroll 1
    for (int k = 0; k < nch; ++k) {
        CP_WAIT(1);
        __syncthreads();
        if (k + 2 < nch) load_chunk((k + 2) % 3, k + 2);

        const uint32_t base = sb + (k % 3) * STAGE_P;
        const uint32_t sAh = base, sAl = base + MAT_BYTES;
        const uint32_t sW = base + 2 * MAT_BYTES;

#pragma unroll
        for (int kg = 0; kg < 2; ++kg) {
            uint32_t ah[2][4], al[2][4], bw[4][4];
#pragma unroll
            for (int mt = 0; mt < 2; ++mt) {
                ldsm4(ah[mt], frag_addr(sAh, warp_m * 32 + mt * 16, kg, lane));
                ldsm4(al[mt], frag_addr(sAl, warp_m * 32 + mt * 16, kg, lane));
            }
#pragma unroll
            for (int ng = 0; ng < 4; ++ng)
                ldsm4(bw[ng], frag_addr(sW, warp_n * 64 + ng * 16, kg, lane));
#pragma unroll
            for (int term = 0; term < 2; ++term)
#pragma unroll
                for (int mt = 0; mt < 2; ++mt)
#pragma unroll
                    for (int ng = 0; ng < 4; ++ng)
#pragma unroll
                        for (int h = 0; h < 2; ++h) {
                            const uint32_t* a = term ? al[mt] : ah[mt];
                            mma16816_f16(acc[mt][ng * 2 + h], a,
                                         bw[ng][h], bw[ng][h + 2]);
                        }
        }
    }
}

// fp16 single x single mainloop (scores): 128x128, K-chunk 64
__device__ __forceinline__ void f16_mainloop(
    uint32_t sb, int tid, int lane, int warp_m, int warp_n,
    const __half* A, const __half* B, int ldk, int nch, float acc[2][8][4])
{
    const __half* mats[2] = {A, B};
    const int rr0 = tid >> 3, cc0 = tid & 7;

    auto load_chunk = [&](int slot, int k) {
        const uint32_t base = sb + slot * STAGEA;
        const long koff = (long)k * 64;
#pragma unroll
        for (int mat = 0; mat < 2; ++mat) {
            const __half* g = mats[mat] + koff;
            const uint32_t mb = base + mat * MAT2_BYTES;
#pragma unroll
            for (int i = 0; i < 4; ++i) {
                const int row = rr0 + i * 32;
                CP_ASYNC16(tile2_addr(mb, row, cc0), g + (long)row * ldk + cc0 * 8);
            }
        }
        CP_COMMIT();
    };

    load_chunk(0, 0);
    load_chunk(1, 1);

#pragma unroll 1
    for (int k = 0; k < nch; ++k) {
        CP_WAIT(1);
        __syncthreads();
        if (k + 2 < nch) load_chunk((k + 2) % 3, k + 2);

        const uint32_t base = sb + (k % 3) * STAGEA;
        const uint32_t sA = base;
        const uint32_t sB = base + MAT2_BYTES;

#pragma unroll
        for (int kg = 0; kg < 4; ++kg) {
            uint32_t af[2][4], bfr[4][4];
#pragma unroll
            for (int mt = 0; mt < 2; ++mt)
                ldsm4(af[mt], frag2_addr(sA, warp_m * 32 + mt * 16, kg, lane));
#pragma unroll
            for (int ng = 0; ng < 4; ++ng)
                ldsm4(bfr[ng], frag2_addr(sB, warp_n * 64 + ng * 16, kg, lane));
#pragma unroll
            for (int mt = 0; mt < 2; ++mt)
#pragma unroll
                for (int ng = 0; ng < 4; ++ng)
#pragma unroll
                    for (int h = 0; h < 2; ++h)
                        mma16816_f16(acc[mt][ng * 2 + h], af[mt],
                                     bfr[ng][h], bfr[ng][h + 2]);
        }
    }
}

// ---------------------------------------------------------------------------
// mega kernel.  Batch-pipelined grid layout:
// [0,256)   prep inputs (64 rows each)
// [256,288) prep W
// then per batch b (chunk of 416 blocks at 288 + b*416):
//   [0,48)    proj-L for batch b (bx 0..5, by8 0..7)
//   [48,96)   proj-R for batch b
//   [96,160)  scores(b)
//   [160,224) transform(b)
//   [224,416) apply(b) (dir0 96, dir1 96)
// total = 288 + 8*416 = 3616
// ---------------------------------------------------------------------------
__global__ __launch_bounds__(256, 2) void mega(
    const float* __restrict__ lhs, const float* __restrict__ rhs,
    const float* __restrict__ Wl, const float* __restrict__ Wr,
    float* __restrict__ out)
{
    extern __shared__ char smem[];
    const uint32_t sb = smem_to_u32(smem);
    const int tid = threadIdx.x;
    const int lane = tid & 31;
    const int wid = tid >> 5;
    const int idx = blockIdx.x;

    if (idx < 256) {
        // =================== PREP inputs (64 rows) ===================
        const int side = idx >> 7, q64 = idx & 127;
        const int b = q64 >> 4, l0v = (q64 & 15) * 64;
        const float* X = (side ? rhs : lhs) + ((size_t)b * LL + l0v) * DD;
        __half* Xh = (side ? s_rhs_h : s_lhs_h) + ((size_t)b * LL + l0v) * DD;
        __half* Xl = (side ? s_rhs_l : s_lhs_l) + ((size_t)b * LL + l0v) * DD;
        __half* XT = (side ? s_rhsT_h : s_lhsT_h) + (size_t)b * DD * LL + l0v;
        float* ob = out + (side ? (size_t)BB * LL * 1536 : 0)
                    + ((size_t)b * LL + l0v) * 1536;
        __half* tr = (__half*)smem;   // [32][72]

#pragma unroll 1
        for (int t = 0; t < 24; ++t) {
            const int d0 = t * 32;
#pragma unroll
            for (int i = 0; i < 2; ++i) {
                const int fi = tid + i * 256;   // 0..511
                const int row = fi >> 3, q = fi & 7;
                const float4 v = *(const float4*)(X + (size_t)row * DD + d0 + q * 4);
                const float vv[4] = {v.x, v.y, v.z, v.w};
                uint32_t hp[2], lp[2];
#pragma unroll
                for (int j = 0; j < 2; ++j) {
                    const __half h0 = __float2half(vv[2 * j]);
                    const __half h1 = __float2half(vv[2 * j + 1]);
                    const __half lo0 = __float2half(vv[2 * j] - __half2float(h0));
                    const __half lo1 = __float2half(vv[2 * j + 1] - __half2float(h1));
                    __half2 hh; hh.x = h0; hh.y = h1;
                    __half2 llv; llv.x = lo0; llv.y = lo1;
                    hp[j] = *(uint32_t*)&hh; lp[j] = *(uint32_t*)&llv;
                }
                *(uint2*)(Xh + (size_t)row * DD + d0 + q * 4) = make_uint2(hp[0], hp[1]);
                *(uint2*)(Xl + (size_t)row * DD + d0 + q * 4) = make_uint2(lp[0], lp[1]);
                *(float4*)(ob + (size_t)row * 1536 + d0 + q * 4) = v;
#pragma unroll
                for (int j = 0; j < 4; ++j)
                    tr[(q * 4 + j) * 72 + row] = __float2half(vv[j]);
            }
            __syncthreads();
            {
                const int d = tid >> 3, c = tid & 7;     // 32 d x 8 c (8 halfs)
                const float4 w0 = *(float4*)&tr[d * 72 + c * 8];
                *(float4*)(XT + (size_t)(d0 + d) * LL + c * 8) = w0;
            }
            __syncthreads();
        }
        __threadfence();
        __syncthreads();
        if (tid == 0) {
            atomicAdd(&c_all[(side ? CI_PREP_R : CI_PREP_L) + (q64 >> 1)], 1);
            atomicAdd(&c_all[CI_XT + side * 8 + b], 1);
        }

    } else if (idx < 288) {
        // =================== PREP W (fp16 single) ===================
        const int wb = idx - 256;   // 0..31
#pragma unroll 1
        for (int w = 0; w < 2; ++w) {
            const float* W = w ? Wr : Wl;
            __half* Wh = w ? s_Wr_h : s_Wl_h;
#pragma unroll 1
            for (int i = 0; i < 18; ++i) {
                const long f = (long)wb * 4608 + i * 256 + tid;
                const float4 v = *(const float4*)(W + f * 4);
                __half2 a; a.x = __float2half(v.x); a.y = __float2half(v.y);
                __half2 b; b.x = __float2half(v.z); b.y = __float2half(v.w);
                *(uint2*)(Wh + f * 4) = make_uint2(*(uint32_t*)&a, *(uint32_t*)&b);
            }
        }
        __threadfence();
        __syncthreads();
        if (tid == 0) atomicAdd(&c_all[CI_W], 1);

    } else {
        const int c = idx - 288;
        const int bch = c / 416;     // batch
        const int r = c % 416;       // phase-slot within batch chunk

        if (r < 96) {
            // =================== PROJ (fp16 x2) ===================
            const int warp_m = wid & 3, warp_n = wid >> 2;
            const int z = r / 48;          // 0 = L, 1 = R
            const int rr = r % 48;
            const int bx = rr % 6;
            const int by = bch * 8 + rr / 6;

            if (tid == 0) {
                wait_ge(&c_all[(z ? CI_PREP_R : CI_PREP_L) + by], 2);
                wait_ge(&c_all[CI_W], 32);
            }
            __syncthreads();

            const __half* Ah = (z ? s_rhs_h : s_lhs_h) + (long)by * 128 * DD;
            const __half* Al = (z ? s_rhs_l : s_lhs_l) + (long)by * 128 * DD;
            const __half* Wh = (z ? s_Wr_h : s_Wl_h) + (long)bx * 128 * DD;
            __half* Cd = z ? g_R_h : g_L_h;

            float acc[2][8][4];
#pragma unroll
            for (int i = 0; i < 2; ++i)
#pragma unroll
                for (int j = 0; j < 8; ++j)
#pragma unroll
                    for (int q = 0; q < 4; ++q) acc[i][j][q] = 0.0f;

            f16x2_mainloop(sb, tid, lane, warp_m, warp_n, Ah, Al, Wh, DD, DD / 32, acc);

            const int rbase = by * 128 + warp_m * 32 + (lane >> 2);
            const int cbase = bx * 128 + warp_n * 64 + (lane & 3) * 2;
#pragma unroll
            for (int mt = 0; mt < 2; ++mt)
#pragma unroll
                for (int nt = 0; nt < 8; ++nt)
#pragma unroll
                    for (int half = 0; half < 2; ++half) {
                        const long rw = rbase + mt * 16 + half * 8;
                        const long cw = cbase + nt * 8;
                        __half2 hh;
                        hh.x = __float2half(fast_tanh(acc[mt][nt][half * 2 + 0]));
                        hh.y = __float2half(fast_tanh(acc[mt][nt][half * 2 + 1]));
                        *(uint32_t*)(Cd + rw * DD + cw) = *(uint32_t*)&hh;
                    }

            __threadfence();
            __syncthreads();
            if (tid == 0) atomicAdd(&c_all[CI_PROJ + z * 64 + by], 1);

        } else if (r < 160) {
            // =================== SCORES (fp16 x fp16) ===================
            const int warp_m = wid & 3, warp_n = wid >> 2;
            const int s = r - 96;
            const int x = s & 7, y = s >> 3, bz = bch;

            if (tid == 0) {
                wait_ge(&c_all[CI_PROJ + bz * 8 + y], 6);
                wait_ge(&c_all[CI_PROJ + 64 + bz * 8 + x], 6);
            }
            __syncthreads();

            const __half* A = g_L_h + ((long)bz * LL + (long)y * 128) * DD;
            const __half* B = g_R_h + ((long)bz * LL + (long)x * 128) * DD;

            float acc[2][8][4];
#pragma unroll
            for (int i = 0; i < 2; ++i)
#pragma unroll
                for (int j = 0; j < 8; ++j)
#pragma unroll
                    for (int q = 0; q < 4; ++q) acc[i][j][q] = 0.0f;

            f16_mainloop(sb, tid, lane, warp_m, warp_n, A, B, DD, DD / 64, acc);

            const int rbase = y * 128 + warp_m * 32 + (lane >> 2);
            const int cbase = x * 128 + warp_n * 64 + (lane & 3) * 2;
            float* Sp = g_S + (long)bz * LL * LL;
#pragma unroll
            for (int mt = 0; mt < 2; ++mt)
#pragma unroll
                for (int nt = 0; nt < 8; ++nt) {
                    const long rw = rbase + mt * 16;
                    const long cw = cbase + nt * 8;
                    *(float2*)(Sp + rw * LL + cw) = make_float2(acc[mt][nt][0], acc[mt][nt][1]);
                    *(float2*)(Sp + (rw + 8) * LL + cw) = make_float2(acc[mt][nt][2], acc[mt][nt][3]);
                }

            // fused softmax partial stats (reuse smem)
            __syncthreads();
            float2* sm_row = (float2*)smem;
            float2* sm_col = ((float2*)smem) + 256;

#pragma unroll
            for (int mt = 0; mt < 2; ++mt)
#pragma unroll
                for (int half = 0; half < 2; ++half) {
                    float m = -1e30f;
#pragma unroll
                    for (int nt = 0; nt < 8; ++nt) {
                        m = fmaxf(m, acc[mt][nt][half * 2 + 0]);
                        m = fmaxf(m, acc[mt][nt][half * 2 + 1]);
                    }
                    float sv = 0.0f;
#pragma unroll
                    for (int nt = 0; nt < 8; ++nt) {
                        sv += __expf(acc[mt][nt][half * 2 + 0] - m);
                        sv += __expf(acc[mt][nt][half * 2 + 1] - m);
                    }
#pragma unroll
                    for (int o = 1; o <= 2; o <<= 1) {
                        float om = __shfl_xor_sync(0xffffffffu, m, o);
                        float os = __shfl_xor_sync(0xffffffffu, sv, o);
                        merge_ms(m, sv, om, os);
                    }
                    if ((lane & 3) == 0) {
                        const int rowl = warp_m * 32 + mt * 16 + half * 8 + (lane >> 2);
                        sm_row[warp_n * 128 + rowl] = make_float2(m, sv);
                    }
                }

#pragma unroll
            for (int nt = 0; nt < 8; ++nt)
#pragma unroll
                for (int cc = 0; cc < 2; ++cc) {
                    const float v0 = acc[0][nt][cc] * INV_SCALE;
                    const float v1 = acc[0][nt][2 + cc] * INV_SCALE;
                    const float v2 = acc[1][nt][cc] * INV_SCALE;
                    const float v3 = acc[1][nt][2 + cc] * INV_SCALE;
                    float m = fmaxf(fmaxf(v0, v1), fmaxf(v2, v3));
                    float sv = __expf(v0 - m) + __expf(v1 - m) +
                               __expf(v2 - m) + __expf(v3 - m);
#pragma unroll
                    for (int o = 4; o <= 16; o <<= 1) {
                        float om = __shfl_xor_sync(0xffffffffu, m, o);
                        float os = __shfl_xor_sync(0xffffffffu, sv, o);
                        merge_ms(m, sv, om, os);
                    }
                    if ((lane >> 2) == 0) {
                        const int coll = warp_n * 64 + nt * 8 + (lane & 3) * 2 + cc;
                        sm_col[warp_m * 128 + coll] = make_float2(m, sv);
                    }
                }

            __syncthreads();
            if (tid < 128) {
                float2 a = sm_row[tid];
                float2 b = sm_row[128 + tid];
                merge_ms(a.x, a.y, b.x, b.y);
                g_prow[x][(long)bz * LL + y * 128 + tid] = a;

                float2 ac = sm_col[tid];
#pragma unroll
                for (int w = 1; w < 4; ++w) {
                    float2 bc = sm_col[w * 128 + tid];
                    merge_ms(ac.x, ac.y, bc.x, bc.y);
                }
                g_pcol[y][(long)bz * LL + x * 128 + tid] = ac;
            }

            __threadfence();
            __syncthreads();
            if (tid == 0) {
                atomicAdd(&c_all[CI_SROW + bz * 8 + y], 1);
                atomicAdd(&c_all[CI_SCOL + bz * 8 + x], 1);
            }

        } else if (r < 224) {
            // =================== TRANSFORM ===================
            const int t = r - 160;
            const int xb = t & 7, yb = t >> 3, bz = bch;

            if (tid == 0) {
                wait_ge(&c_all[CI_SROW + bz * 8 + yb], 8);
                wait_ge(&c_all[CI_SCOL + bz * 8 + xb], 8);
            }
            __syncthreads();

            float* rowc_s = (float*)smem;             // 128
            float* colc_s = rowc_s + 128;             // 128
            __half* tr = (__half*)(colc_s + 128);     // [128][130]

            if (tid < 128) {
                float m = -1e30f, sv = 0.0f;
#pragma unroll
                for (int p = 0; p < 8; ++p) {
                    const float2 v = g_prow[p][(long)bz * LL + yb * 128 + tid];
                    merge_ms(m, sv, v.x, v.y);
                }
                rowc_s[tid] = m + __logf(sv);
            } else {
                const int cc = tid - 128;
                float m = -1e30f, sv = 0.0f;
#pragma unroll
                for (int p = 0; p < 8; ++p) {
                    const float2 v = g_pcol[p][(long)bz * LL + xb * 128 + cc];
                    merge_ms(m, sv, v.x, v.y);
                }
                colc_s[cc] = m + __logf(sv);
            }
            __syncthreads();

            const size_t base = (size_t)bz * LL * LL;
#pragma unroll 4
            for (int i = 0; i < 64; ++i) {
                const int rr2 = i * 2 + (tid >> 7);
                const int cc = tid & 127;
                const size_t gi = base + (size_t)(yb * 128 + rr2) * LL + xb * 128 + cc;
                const float sval = g_S[gi];
                g_P1[gi] = __float2half(__expf(sval - rowc_s[rr2]));
                tr[cc * 130 + rr2] = __float2half(__expf(sval * INV_SCALE - colc_s[cc]));
            }
            __syncthreads();
#pragma unroll 4
            for (int i = 0; i < 64; ++i) {
                const int rr2 = i * 2 + (tid >> 7);
                const int cc = tid & 127;
                g_P2T[base + (size_t)(xb * 128 + rr2) * LL + yb * 128 + cc] = tr[rr2 * 130 + cc];
            }

            __threadfence();
            __syncthreads();
            if (tid == 0) {
                atomicAdd(&c_all[CI_P1 + bz * 8 + yb], 1);
                atomicAdd(&c_all[CI_P2 + bz * 8 + xb], 1);
            }

        } else {
            // =================== APPLY (128x64 tiles) ===================
            const int warp_m = wid & 3, warp_n = wid >> 2;
            const int a = r - 224;           // 0..191
            const int dir = a / 96;
            const int aa = a % 96;
            const int x = aa % 12;
            const int y = aa / 12;
            const int bz = bch;

            if (tid == 0) {
                wait_ge(dir ? &c_all[CI_P2 + bz * 8 + y] : &c_all[CI_P1 + bz * 8 + y], 8);
                wait_ge(&c_all[CI_XT + (dir ? 0 : 8) + bz], 16);
            }
            __syncthreads();

            const __half* P = dir ? g_P2T : g_P1;
            const __half* V = dir ? s_lhsT_h : s_rhsT_h;
            float* outp = dir ? out + (size_t)BB * LL * 1536 : out;

            const __half* Ap = P + (long)bz * LL * LL + (long)y * 128 * LL;
            const __half* Bp = V + (long)bz * DD * LL + (long)x * 64 * LL;

            const int rr0 = tid >> 3, cc0 = tid & 7;

            auto load_chunk = [&](int slot, int k) {
                const uint32_t base = sb + slot * STAGE_AP;
                const long koff = (long)k * 64;
#pragma unroll
                for (int i = 0; i < 4; ++i) {
                    const int row = rr0 + i * 32;
                    CP_ASYNC16(tile2_addr(base, row, cc0), Ap + (long)row * LL + koff + cc0 * 8);
                }
#pragma unroll
                for (int i = 0; i < 2; ++i) {
                    const int row = rr0 + i * 32;
                    CP_ASYNC16(tile2_addr(base + 16384, row, cc0),
                               Bp + (long)row * LL + koff + cc0 * 8);
                }
                CP_COMMIT();
            };

            float acc[2][4][4];
#pragma unroll
            for (int i = 0; i < 2; ++i)
#pragma unroll
                for (int j = 0; j < 4; ++j)
#pragma unroll
                    for (int q = 0; q < 4; ++q) acc[i][j][q] = 0.0f;

            load_chunk(0, 0);
            load_chunk(1, 1);

#pragma unroll 1
            for (int k = 0; k < 16; ++k) {
                CP_WAIT(1);
                __syncthreads();
                if (k + 2 < 16) load_chunk((k + 2) % 3, k + 2);

                const uint32_t base = sb + (k % 3) * STAGE_AP;
                const uint32_t sA = base;
                const uint32_t sB = base + 16384;

#pragma unroll
                for (int kg = 0; kg < 4; ++kg) {
                    uint32_t af[2][4], bfr[2][4];
#pragma unroll
                    for (int mt = 0; mt < 2; ++mt)
                        ldsm4(af[mt], frag2_addr(sA, warp_m * 32 + mt * 16, kg, lane));
#pragma unroll
                    for (int bt = 0; bt < 2; ++bt)
                        ldsm4(bfr[bt], frag2_addr(sB, warp_n * 32 + bt * 16, kg, lane));
#pragma unroll
                    for (int mt = 0; mt < 2; ++mt)
#pragma unroll
                        for (int bt = 0; bt < 2; ++bt)
#pragma unroll
                            for (int h = 0; h < 2; ++h)
                                mma16816_f16(acc[mt][bt * 2 + h], af[mt],
                                             bfr[bt][h], bfr[bt][h + 2]);
                }
            }
            __syncthreads();

            const int rbase = y * 128 + warp_m * 32 + (lane >> 2);
            const int cbase = x * 64 + warp_n * 32 + (lane & 3) * 2;
            float* Ob = outp + (long)bz * LL * 1536 + DD;
#pragma unroll
            for (int mt = 0; mt < 2; ++mt)
#pragma unroll
                for (int nt = 0; nt < 4; ++nt) {
                    const long rw = rbase + mt * 16;
                    const long cw = cbase + nt * 8;
                    float* Cp = Ob + rw * 1536 + cw;
                    *(float2*)Cp = make_float2(acc[mt][nt][0], acc[mt][nt][1]);
                    *(float2*)(Cp + 8L * 1536) = make_float2(acc[mt][nt][2], acc[mt][nt][3]);
                }
        }
    }
}

// counter reset (must run before mega every replay)
__global__ void reset_ctr()
{
    const int i = blockIdx.x * blockDim.x + threadIdx.x;
    if (i < NCTR) c_all[i] = 0;
}

// ---------------------------------------------------------------------------
// launch
// ---------------------------------------------------------------------------
extern "C" void kernel_launch(void* const* d_in, const int* in_sizes, int n_in,
                              void* d_out, int out_size)
{
    const float* lhs = (const float*)d_in[0];
    const float* rhs = (const float*)d_in[1];
    const float* Wl  = (const float*)d_in[2];
    const float* Wr  = (const float*)d_in[3];
    float* out = (float*)d_out;

    cudaFuncSetAttribute(mega, cudaFuncAttributeMaxDynamicSharedMemorySize, SMEM_DYN);

    reset_ctr<<<3, 256>>>();
    mega<<<3616, 256, SMEM_DYN>>>(lhs, rhs, Wl, Wr, out);
}